// round 1
// baseline (speedup 1.0000x reference)
#include <cuda_runtime.h>
#include <math.h>

// Problem constants
#define BB 128      // batch
#define TT 128      // time steps
#define FF 128      // features
#define DD 512      // hidden
#define NG 2048     // 4*D
#define KC 32       // K-chunk

// Scratch (device globals — no allocation allowed)
__device__ float g_h [BB*DD];
__device__ float g_c [BB*DD];
__device__ float g_h0[BB*DD];
__device__ float g_c0[BB*DD];
__device__ float g_hA[BB*DD];
__device__ float g_cA[BB*DD];
__device__ float g_hB[BB*DD];
__device__ float g_cB[BB*DD];
__device__ float g_Wsum[DD*NG];

__device__ __forceinline__ float sigmoidf_(float x) { return 1.0f / (1.0f + expf(-x)); }

// Wsum = enc_W1 + enc_U1  (valid because encoder layer 1 has x == h)
__global__ void add_mats_kernel(const float* __restrict__ a, const float* __restrict__ b,
                                float* __restrict__ o, int n) {
    int i = blockIdx.x * blockDim.x + threadIdx.x;
    if (i < n) o[i] = a[i] + b[i];
}

// Fused LSTM cell: z = X@W (K1 cols, row stride ldx) + H@U (K2 cols, row stride DD) + bias
// then i,f,o = sigmoid; g = relu; c2 = f*cin + i*g; h2 = o*relu(c2)
// Grid: 128 blocks. Block j owns gate-columns [j*4, j*4+4) i.e. z cols g*512 + j*4 + {0..3}.
// 256 threads; thread (gco = tid&3, rb = tid>>2) accumulates rows rb and rb+64 for all 4 gates.
__global__ __launch_bounds__(256, 1) void lstm_cell_kernel(
    const float* __restrict__ X, int ldx, int K1, const float* __restrict__ W,
    const float* __restrict__ H, const float* __restrict__ U, int K2,
    const float* __restrict__ bias, const float* __restrict__ cin,
    float* __restrict__ hout, float* __restrict__ cout)
{
    __shared__ float As[BB][KC + 1];   // staged input rows (padded)
    __shared__ float Bs[KC][16];       // staged weight cols (4 gates x 4 cols)

    const int tid = threadIdx.x;
    const int j   = blockIdx.x;      // gate-column group
    const int gco = tid & 3;         // which of the 4 cols in the group
    const int rb  = tid >> 2;        // 0..63 ; rows rb and rb+64

    float acc0[4] = {0.f, 0.f, 0.f, 0.f};
    float acc1[4] = {0.f, 0.f, 0.f, 0.f};

    #pragma unroll
    for (int phase = 0; phase < 2; ++phase) {
        const float* A  = phase ? H  : X;
        const float* Bm = phase ? U  : W;
        const int    K  = phase ? K2 : K1;
        const int    lda = phase ? DD : ldx;

        for (int k0 = 0; k0 < K; k0 += KC) {
            // Stage A chunk: 128 rows x 32 k (coalesced 128B segments)
            #pragma unroll
            for (int idx = tid; idx < BB * KC; idx += 256) {
                int r = idx >> 5, k = idx & 31;
                As[r][k] = A[r * lda + k0 + k];
            }
            // Stage B chunk: 32 k-rows x 16 cols (4 gates x 4 contiguous cols)
            {
                int kq = tid >> 4, ci = tid & 15;
                int g  = ci >> 2, cc = ci & 3;
                #pragma unroll
                for (int p = 0; p < 2; ++p) {
                    int kk = kq + p * 16;
                    Bs[kk][ci] = Bm[(size_t)(k0 + kk) * NG + g * DD + j * 4 + cc];
                }
            }
            __syncthreads();

            #pragma unroll
            for (int k = 0; k < KC; ++k) {
                float a0 = As[rb][k];
                float a1 = As[rb + 64][k];
                #pragma unroll
                for (int g = 0; g < 4; ++g) {
                    float u = Bs[k][g * 4 + gco];
                    acc0[g] += a0 * u;
                    acc1[g] += a1 * u;
                }
            }
            __syncthreads();
        }
    }

    const int col = j * 4 + gco;
    const float bi = bias[col];
    const float bf = bias[DD + col];
    const float bg = bias[2 * DD + col];
    const float bo = bias[3 * DD + col];

    {
        int r = rb;
        float i = sigmoidf_(acc0[0] + bi);
        float f = sigmoidf_(acc0[1] + bf);
        float g = fmaxf(acc0[2] + bg, 0.f);
        float o = sigmoidf_(acc0[3] + bo);
        float c2 = f * cin[r * DD + col] + i * g;
        cout[r * DD + col] = c2;
        hout[r * DD + col] = o * fmaxf(c2, 0.f);
    }
    {
        int r = rb + 64;
        float i = sigmoidf_(acc1[0] + bi);
        float f = sigmoidf_(acc1[1] + bf);
        float g = fmaxf(acc1[2] + bg, 0.f);
        float o = sigmoidf_(acc1[3] + bo);
        float c2 = f * cin[r * DD + col] + i * g;
        cout[r * DD + col] = c2;
        hout[r * DD + col] = o * fmaxf(c2, 0.f);
    }
}

// out[b, col] = H[b,:] @ Wd[:,col] + bd[col]; out base already offset to the right time slice.
// 64 blocks x 256 threads; each thread one output. Warp = one row -> H broadcast, Wd coalesced.
__global__ __launch_bounds__(256, 1) void dense_kernel(
    const float* __restrict__ H, const float* __restrict__ Wd,
    const float* __restrict__ bd, float* __restrict__ out)
{
    int idx = blockIdx.x * 256 + threadIdx.x;   // 0..16383
    int row = idx >> 7;
    int col = idx & 127;
    const float* h = H + row * DD;
    float a0 = 0.f, a1 = 0.f, a2 = 0.f, a3 = 0.f;
    #pragma unroll 4
    for (int k = 0; k < DD; k += 4) {
        a0 += h[k + 0] * Wd[(k + 0) * FF + col];
        a1 += h[k + 1] * Wd[(k + 1) * FF + col];
        a2 += h[k + 2] * Wd[(k + 2) * FF + col];
        a3 += h[k + 3] * Wd[(k + 3) * FF + col];
    }
    out[(size_t)row * TT * FF + col] = (a0 + a1) + (a2 + a3) + bd[col];
}

extern "C" void kernel_launch(void* const* d_in, const int* in_sizes, int n_in,
                              void* d_out, int out_size)
{
    const float* enc_in  = (const float*)d_in[0];
    const float* dec_in  = (const float*)d_in[1];
    const float* enc_W0  = (const float*)d_in[2];
    const float* enc_U0  = (const float*)d_in[3];
    const float* enc_b0  = (const float*)d_in[4];
    const float* enc_W1  = (const float*)d_in[5];
    const float* enc_U1  = (const float*)d_in[6];
    const float* enc_b1  = (const float*)d_in[7];
    const float* dec_W0  = (const float*)d_in[8];
    const float* dec_U0  = (const float*)d_in[9];
    const float* dec_b0  = (const float*)d_in[10];
    const float* dec_W1  = (const float*)d_in[11];
    const float* dec_U1  = (const float*)d_in[12];
    const float* dec_b1  = (const float*)d_in[13];
    const float* dense_W = (const float*)d_in[14];
    const float* dense_b = (const float*)d_in[15];
    float* out = (float*)d_out;

    float *h, *c, *h0, *c0, *hA, *cA, *hB, *cB, *Wsum;
    cudaGetSymbolAddress((void**)&h,    g_h);
    cudaGetSymbolAddress((void**)&c,    g_c);
    cudaGetSymbolAddress((void**)&h0,   g_h0);
    cudaGetSymbolAddress((void**)&c0,   g_c0);
    cudaGetSymbolAddress((void**)&hA,   g_hA);
    cudaGetSymbolAddress((void**)&cA,   g_cA);
    cudaGetSymbolAddress((void**)&hB,   g_hB);
    cudaGetSymbolAddress((void**)&cB,   g_cB);
    cudaGetSymbolAddress((void**)&Wsum, g_Wsum);

    // Initial hidden state = 0
    cudaMemsetAsync(h, 0, BB * DD * sizeof(float));
    cudaMemsetAsync(c, 0, BB * DD * sizeof(float));

    // Wsum = enc_W1 + enc_U1
    {
        int n = DD * NG;
        add_mats_kernel<<<(n + 255) / 256, 256>>>(enc_W1, enc_U1, Wsum, n);
    }

    const int ldt = TT * FF;   // row stride when indexing a (B,T,F) tensor's time slice

    // ---------------- Encoder: 128 steps, 2 layers ----------------
    for (int t = 0; t < TT; ++t) {
        // layer 0: z = x_t@W0 + h@U0 + b0
        lstm_cell_kernel<<<128, 256>>>(enc_in + (size_t)t * FF, ldt, FF, enc_W0,
                                       h, enc_U0, DD,
                                       enc_b0, c, h0, c0);
        // layer 1: x == h == h0  =>  z = h0@(W1+U1) + b1
        lstm_cell_kernel<<<128, 256>>>(h0, DD, DD, Wsum,
                                       (const float*)nullptr, (const float*)nullptr, 0,
                                       enc_b1, c0, h, c);
    }

    // ---------------- Decoder: 128 steps, 2 layers + dense ----------------
    for (int t = 0; t < TT; ++t) {
        const float* hcur = (t == 0) ? h : ((t & 1) ? hA : hB);
        const float* ccur = (t == 0) ? c : ((t & 1) ? cA : cB);
        float* hnext = (t & 1) ? hB : hA;
        float* cnext = (t & 1) ? cB : cA;

        // input: previous dense output (stored at out[:, T-t, :]) or dec_in[:,0,:]
        const float* X = (t == 0) ? dec_in : (out + (size_t)(TT - t) * FF);

        // layer 0: reads OLD h,c; its c2 is discarded by the reference
        lstm_cell_kernel<<<128, 256>>>(X, ldt, FF, dec_W0,
                                       hcur, dec_U0, DD,
                                       dec_b0, ccur, h0, c0);
        // layer 1: x = layer0 h, but h,c = OLD carry (reference quirk)
        lstm_cell_kernel<<<128, 256>>>(h0, DD, DD, dec_W1,
                                       hcur, dec_U1, DD,
                                       dec_b1, ccur, hnext, cnext);
        // dense: out_t -> out[:, T-1-t, :]  (reference reverses outs)
        dense_kernel<<<64, 256>>>(hnext, dense_W, dense_b,
                                  out + (size_t)(TT - 1 - t) * FF);
    }
}

// round 2
// speedup vs baseline: 1.0023x; 1.0023x over previous
#include <cuda_runtime.h>
#include <math.h>

// Problem constants
#define BB 128      // batch
#define TT 128      // time steps
#define FF 128      // features
#define DD 512      // hidden
#define NG 2048     // 4*D
#define KC 32       // K-chunk

// Scratch (device globals — no allocation allowed)
__device__ float g_h [BB*DD];
__device__ float g_c [BB*DD];
__device__ float g_h0[BB*DD];
__device__ float g_c0[BB*DD];
__device__ float g_hA[BB*DD];
__device__ float g_cA[BB*DD];
__device__ float g_hB[BB*DD];
__device__ float g_cB[BB*DD];
__device__ float g_Wsum[DD*NG];

__device__ __forceinline__ float sigmoidf_(float x) { return 1.0f / (1.0f + expf(-x)); }

// Wsum = enc_W1 + enc_U1  (valid because encoder layer 1 has x == h)
__global__ void add_mats_kernel(const float* __restrict__ a, const float* __restrict__ b,
                                float* __restrict__ o, int n) {
    int i = blockIdx.x * blockDim.x + threadIdx.x;
    if (i < n) o[i] = a[i] + b[i];
}

// Fused LSTM cell: z = X@W (K1 cols, row stride ldx) + H@U (K2 cols, row stride DD) + bias
// then i,f,o = sigmoid; g = relu; c2 = f*cin + i*g; h2 = o*relu(c2)
// Grid: 128 blocks. Block j owns gate-columns [j*4, j*4+4) i.e. z cols g*512 + j*4 + {0..3}.
// 256 threads; thread (gco = tid&3, rb = tid>>2) accumulates rows rb and rb+64 for all 4 gates.
__global__ __launch_bounds__(256, 1) void lstm_cell_kernel(
    const float* __restrict__ X, int ldx, int K1, const float* __restrict__ W,
    const float* __restrict__ H, const float* __restrict__ U, int K2,
    const float* __restrict__ bias, const float* __restrict__ cin,
    float* __restrict__ hout, float* __restrict__ cout)
{
    __shared__ float As[BB][KC + 1];   // staged input rows (padded)
    __shared__ float Bs[KC][16];       // staged weight cols (4 gates x 4 cols)

    const int tid = threadIdx.x;
    const int j   = blockIdx.x;      // gate-column group
    const int gco = tid & 3;         // which of the 4 cols in the group
    const int rb  = tid >> 2;        // 0..63 ; rows rb and rb+64

    float acc0[4] = {0.f, 0.f, 0.f, 0.f};
    float acc1[4] = {0.f, 0.f, 0.f, 0.f};

    #pragma unroll
    for (int phase = 0; phase < 2; ++phase) {
        const float* A  = phase ? H  : X;
        const float* Bm = phase ? U  : W;
        const int    K  = phase ? K2 : K1;
        const int    lda = phase ? DD : ldx;

        for (int k0 = 0; k0 < K; k0 += KC) {
            // Stage A chunk: 128 rows x 32 k (coalesced 128B segments)
            #pragma unroll
            for (int idx = tid; idx < BB * KC; idx += 256) {
                int r = idx >> 5, k = idx & 31;
                As[r][k] = A[r * lda + k0 + k];
            }
            // Stage B chunk: 32 k-rows x 16 cols (4 gates x 4 contiguous cols)
            {
                int kq = tid >> 4, ci = tid & 15;
                int g  = ci >> 2, cc = ci & 3;
                #pragma unroll
                for (int p = 0; p < 2; ++p) {
                    int kk = kq + p * 16;
                    Bs[kk][ci] = Bm[(size_t)(k0 + kk) * NG + g * DD + j * 4 + cc];
                }
            }
            __syncthreads();

            #pragma unroll
            for (int k = 0; k < KC; ++k) {
                float a0 = As[rb][k];
                float a1 = As[rb + 64][k];
                #pragma unroll
                for (int g = 0; g < 4; ++g) {
                    float u = Bs[k][g * 4 + gco];
                    acc0[g] += a0 * u;
                    acc1[g] += a1 * u;
                }
            }
            __syncthreads();
        }
    }

    const int col = j * 4 + gco;
    const float bi = bias[col];
    const float bf = bias[DD + col];
    const float bg = bias[2 * DD + col];
    const float bo = bias[3 * DD + col];

    {
        int r = rb;
        float i = sigmoidf_(acc0[0] + bi);
        float f = sigmoidf_(acc0[1] + bf);
        float g = fmaxf(acc0[2] + bg, 0.f);
        float o = sigmoidf_(acc0[3] + bo);
        float c2 = f * cin[r * DD + col] + i * g;
        cout[r * DD + col] = c2;
        hout[r * DD + col] = o * fmaxf(c2, 0.f);
    }
    {
        int r = rb + 64;
        float i = sigmoidf_(acc1[0] + bi);
        float f = sigmoidf_(acc1[1] + bf);
        float g = fmaxf(acc1[2] + bg, 0.f);
        float o = sigmoidf_(acc1[3] + bo);
        float c2 = f * cin[r * DD + col] + i * g;
        cout[r * DD + col] = c2;
        hout[r * DD + col] = o * fmaxf(c2, 0.f);
    }
}

// out[b, col] = H[b,:] @ Wd[:,col] + bd[col]; out base already offset to the right time slice.
// 64 blocks x 256 threads; each thread one output. Warp = one row -> H broadcast, Wd coalesced.
__global__ __launch_bounds__(256, 1) void dense_kernel(
    const float* __restrict__ H, const float* __restrict__ Wd,
    const float* __restrict__ bd, float* __restrict__ out)
{
    int idx = blockIdx.x * 256 + threadIdx.x;   // 0..16383
    int row = idx >> 7;
    int col = idx & 127;
    const float* h = H + row * DD;
    float a0 = 0.f, a1 = 0.f, a2 = 0.f, a3 = 0.f;
    #pragma unroll 4
    for (int k = 0; k < DD; k += 4) {
        a0 += h[k + 0] * Wd[(k + 0) * FF + col];
        a1 += h[k + 1] * Wd[(k + 1) * FF + col];
        a2 += h[k + 2] * Wd[(k + 2) * FF + col];
        a3 += h[k + 3] * Wd[(k + 3) * FF + col];
    }
    out[(size_t)row * TT * FF + col] = (a0 + a1) + (a2 + a3) + bd[col];
}

extern "C" void kernel_launch(void* const* d_in, const int* in_sizes, int n_in,
                              void* d_out, int out_size)
{
    const float* enc_in  = (const float*)d_in[0];
    const float* dec_in  = (const float*)d_in[1];
    const float* enc_W0  = (const float*)d_in[2];
    const float* enc_U0  = (const float*)d_in[3];
    const float* enc_b0  = (const float*)d_in[4];
    const float* enc_W1  = (const float*)d_in[5];
    const float* enc_U1  = (const float*)d_in[6];
    const float* enc_b1  = (const float*)d_in[7];
    const float* dec_W0  = (const float*)d_in[8];
    const float* dec_U0  = (const float*)d_in[9];
    const float* dec_b0  = (const float*)d_in[10];
    const float* dec_W1  = (const float*)d_in[11];
    const float* dec_U1  = (const float*)d_in[12];
    const float* dec_b1  = (const float*)d_in[13];
    const float* dense_W = (const float*)d_in[14];
    const float* dense_b = (const float*)d_in[15];
    float* out = (float*)d_out;

    float *h, *c, *h0, *c0, *hA, *cA, *hB, *cB, *Wsum;
    cudaGetSymbolAddress((void**)&h,    g_h);
    cudaGetSymbolAddress((void**)&c,    g_c);
    cudaGetSymbolAddress((void**)&h0,   g_h0);
    cudaGetSymbolAddress((void**)&c0,   g_c0);
    cudaGetSymbolAddress((void**)&hA,   g_hA);
    cudaGetSymbolAddress((void**)&cA,   g_cA);
    cudaGetSymbolAddress((void**)&hB,   g_hB);
    cudaGetSymbolAddress((void**)&cB,   g_cB);
    cudaGetSymbolAddress((void**)&Wsum, g_Wsum);

    // Initial hidden state = 0
    cudaMemsetAsync(h, 0, BB * DD * sizeof(float));
    cudaMemsetAsync(c, 0, BB * DD * sizeof(float));

    // Wsum = enc_W1 + enc_U1
    {
        int n = DD * NG;
        add_mats_kernel<<<(n + 255) / 256, 256>>>(enc_W1, enc_U1, Wsum, n);
    }

    const int ldt = TT * FF;   // row stride when indexing a (B,T,F) tensor's time slice

    // ---------------- Encoder: 128 steps, 2 layers ----------------
    for (int t = 0; t < TT; ++t) {
        // layer 0: z = x_t@W0 + h@U0 + b0
        lstm_cell_kernel<<<128, 256>>>(enc_in + (size_t)t * FF, ldt, FF, enc_W0,
                                       h, enc_U0, DD,
                                       enc_b0, c, h0, c0);
        // layer 1: x == h == h0  =>  z = h0@(W1+U1) + b1
        lstm_cell_kernel<<<128, 256>>>(h0, DD, DD, Wsum,
                                       (const float*)nullptr, (const float*)nullptr, 0,
                                       enc_b1, c0, h, c);
    }

    // ---------------- Decoder: 128 steps, 2 layers + dense ----------------
    for (int t = 0; t < TT; ++t) {
        const float* hcur = (t == 0) ? h : ((t & 1) ? hA : hB);
        const float* ccur = (t == 0) ? c : ((t & 1) ? cA : cB);
        float* hnext = (t & 1) ? hB : hA;
        float* cnext = (t & 1) ? cB : cA;

        // input: previous dense output (stored at out[:, T-t, :]) or dec_in[:,0,:]
        const float* X = (t == 0) ? dec_in : (out + (size_t)(TT - t) * FF);

        // layer 0: reads OLD h,c; its c2 is discarded by the reference
        lstm_cell_kernel<<<128, 256>>>(X, ldt, FF, dec_W0,
                                       hcur, dec_U0, DD,
                                       dec_b0, ccur, h0, c0);
        // layer 1: x = layer0 h, but h,c = OLD carry (reference quirk)
        lstm_cell_kernel<<<128, 256>>>(h0, DD, DD, dec_W1,
                                       hcur, dec_U1, DD,
                                       dec_b1, ccur, hnext, cnext);
        // dense: out_t -> out[:, T-1-t, :]  (reference reverses outs)
        dense_kernel<<<64, 256>>>(hnext, dense_W, dense_b,
                                  out + (size_t)(TT - 1 - t) * FF);
    }
}